// round 15
// baseline (speedup 1.0000x reference)
#include <cuda_runtime.h>
#include <cuda_fp16.h>
#include <cstdint>

// ---------------- problem constants ----------------
#define BB   2
#define TT   2048
#define DD   1024
#define HH   16
#define HDIM 64
#define FF   4096
#define ROWS (BB*TT)          // 4096

// ---------------- scratch (device globals) ----------------
__device__ __half g_xa [ROWS*DD];
__device__ __half g_q  [ROWS*DD];
__device__ __half g_k  [ROWS*DD];
__device__ __half g_v  [ROWS*DD];
__device__ __half g_at [ROWS*DD];
__device__ float  g_x1 [ROWS*DD];
__device__ __half g_h  [(size_t)ROWS*FF];
__device__ __half g_wh [(size_t)12*1024*1024];

// ---------------- helpers ----------------
__device__ __forceinline__ uint32_t smem_u32(const void* p) {
    return (uint32_t)__cvta_generic_to_shared(p);
}
__device__ __forceinline__ void mma_f16(float* c, const uint32_t* a,
                                        uint32_t b0, uint32_t b1) {
    asm volatile(
        "mma.sync.aligned.m16n8k16.row.col.f32.f16.f16.f32 "
        "{%0,%1,%2,%3},{%4,%5,%6,%7},{%8,%9},{%0,%1,%2,%3};\n"
        : "+f"(c[0]), "+f"(c[1]), "+f"(c[2]), "+f"(c[3])
        : "r"(a[0]), "r"(a[1]), "r"(a[2]), "r"(a[3]), "r"(b0), "r"(b1));
}
__device__ __forceinline__ void ldsm_x4(uint32_t* r, uint32_t saddr) {
    asm volatile("ldmatrix.sync.aligned.m8n8.x4.shared.b16 {%0,%1,%2,%3}, [%4];"
                 : "=r"(r[0]), "=r"(r[1]), "=r"(r[2]), "=r"(r[3]) : "r"(saddr));
}
__device__ __forceinline__ void ldsm_x4_t(uint32_t* r, uint32_t saddr) {
    asm volatile("ldmatrix.sync.aligned.m8n8.x4.trans.shared.b16 {%0,%1,%2,%3}, [%4];"
                 : "=r"(r[0]), "=r"(r[1]), "=r"(r[2]), "=r"(r[3]) : "r"(saddr));
}
__device__ __forceinline__ void cp16(uint32_t saddr, const void* g) {
    asm volatile("cp.async.cg.shared.global [%0], [%1], 16;\n" :: "r"(saddr), "l"(g));
}

// ---------------- fused weight convert fp32 -> fp16 ----------------
#define CVT_TOTAL 1572864
__global__ __launch_bounds__(256)
void convert_all(const float4* __restrict__ wq, const float4* __restrict__ wk,
                 const float4* __restrict__ wv, const float4* __restrict__ wo,
                 const float4* __restrict__ w1, const float4* __restrict__ w2,
                 uint4* __restrict__ dst) {
    const int nth = gridDim.x * 256;
    for (int i = blockIdx.x * 256 + threadIdx.x; i < CVT_TOTAL; i += nth) {
        const float4* src;
        int off;
        if (i < 524288) {
            int r = i >> 17;
            src = (r == 0) ? wq : (r == 1) ? wk : (r == 2) ? wv : wo;
            off = i & 131071;
        } else if (i < 1048576) {
            src = w1; off = i - 524288;
        } else {
            src = w2; off = i - 1048576;
        }
        float4 a = src[2 * off], b = src[2 * off + 1];
        __half2 h0 = __floats2half2_rn(a.x, a.y);
        __half2 h1 = __floats2half2_rn(a.z, a.w);
        __half2 h2 = __floats2half2_rn(b.x, b.y);
        __half2 h3 = __floats2half2_rn(b.z, b.w);
        uint4 o;
        o.x = *(uint32_t*)&h0; o.y = *(uint32_t*)&h1;
        o.z = *(uint32_t*)&h2; o.w = *(uint32_t*)&h3;
        dst[i] = o;
    }
}

// ---------------- rmsnorm (fp16 output) ----------------
__global__ __launch_bounds__(256)
void rmsnorm_kernel(const float* __restrict__ x, const float* __restrict__ g,
                    __half* __restrict__ out) {
    __shared__ float red[256];
    const int row = blockIdx.x;
    const int tid = threadIdx.x;
    const float4 v = ((const float4*)(x + (size_t)row * DD))[tid];
    float ss = v.x*v.x + v.y*v.y + v.z*v.z + v.w*v.w;
    red[tid] = ss;
    __syncthreads();
    #pragma unroll
    for (int s = 128; s > 0; s >>= 1) {
        if (tid < s) red[tid] += red[tid + s];
        __syncthreads();
    }
    const float norm = rsqrtf(red[0] * (1.0f / DD) + 1e-5f);
    const float4 gv = ((const float4*)g)[tid];
    __half2 h01 = __floats2half2_rn(v.x * norm * gv.x, v.y * norm * gv.y);
    __half2 h23 = __floats2half2_rn(v.z * norm * gv.z, v.w * norm * gv.w);
    uint2 pk; pk.x = *(uint32_t*)&h01; pk.y = *(uint32_t*)&h23;
    ((uint2*)(out + (size_t)row * DD))[tid] = pk;
}

// ---------------- fp16 tensor-core GEMM (R10 config: 256 thr, 16 warps/SM) ----
// C[M,N] = A[M,K] @ W[K,N]. BM=BN=128, BK=64, 2x4 warps, 64x32 warp tile.
#define SGS3 3
#define STG_BYTES 32768
#define GEMM_SMEM (SGS3 * STG_BYTES)

template <int EPI>
__global__ __launch_bounds__(256, 2)
void gemm_f16(const __half* __restrict__ A,
              const __half* __restrict__ B0, const __half* __restrict__ B1,
              const __half* __restrict__ B2,
              void* C0v, void* C1v, void* C2v,
              const float* __restrict__ bias, const float* __restrict__ res,
              int N, int K) {
    extern __shared__ __align__(16) char dynsm[];
    const uint32_t sb = smem_u32(dynsm);

    const __half* Bw = (blockIdx.z == 0) ? B0 : (blockIdx.z == 1 ? B1 : B2);
    void* Cv = (blockIdx.z == 0) ? C0v : (blockIdx.z == 1 ? C1v : C2v);

    const int tid   = threadIdx.x;
    const int lane  = tid & 31;
    const int warp  = tid >> 5;
    const int warpM = warp & 1;
    const int warpN = warp >> 1;       // 0..3
    const int g8    = lane >> 3;
    const int i7    = lane & 7;

    const int bm = blockIdx.y, bn = blockIdx.x;
    const __half* Aq = A  + (size_t)bm * 128 * K;
    const __half* Bq = Bw + bn * 128;

    const int aRow = warpM * 64 + (g8 & 1) * 8 + i7;
    const int aHi  = g8 >> 1;

    int arow[4], ach[4], asw[4], brow[4], bch[4], bsw[4];
    #pragma unroll
    for (int p = 0; p < 4; p++) {
        int idx = tid + p * 256;
        arow[p] = idx >> 3;  ach[p] = idx & 7;
        asw[p]  = ach[p] ^ (arow[p] & 7);
        brow[p] = idx >> 4;  bch[p] = idx & 15;
        bsw[p]  = (bch[p] & 8) | ((bch[p] ^ brow[p]) & 7);
    }

#define ISSUE_STAGE(st, kb)                                                    \
    {                                                                          \
        uint32_t Ab = sb + (st) * STG_BYTES;                                   \
        uint32_t Bb = Ab + 16384;                                              \
        _Pragma("unroll")                                                      \
        for (int p = 0; p < 4; p++) {                                          \
            cp16(Ab + arow[p] * 128 + asw[p] * 16,                             \
                 Aq + (size_t)arow[p] * K + (kb) + ach[p] * 8);                \
            cp16(Bb + brow[p] * 256 + bsw[p] * 16,                             \
                 Bq + (size_t)((kb) + brow[p]) * N + bch[p] * 8);              \
        }                                                                      \
        asm volatile("cp.async.commit_group;\n");                              \
    }

    float c[4][4][4];
    #pragma unroll
    for (int mi = 0; mi < 4; mi++)
        #pragma unroll
        for (int ni = 0; ni < 4; ni++)
            #pragma unroll
            for (int u = 0; u < 4; u++) c[mi][ni][u] = 0.f;

    const int ktiles = K >> 6;

    ISSUE_STAGE(0, 0);
    ISSUE_STAGE(1, 64);

    for (int u = 0; u < ktiles; u++) {
        asm volatile("cp.async.wait_group 1;\n");
        __syncthreads();

        if (u + 2 < ktiles) {
            const int stn = (u + 2) % SGS3;
            ISSUE_STAGE(stn, (u + 2) * 64);
        } else {
            asm volatile("cp.async.commit_group;\n");
        }

        const int st = u % SGS3;
        const uint32_t Ab = sb + st * STG_BYTES;
        const uint32_t Bb = Ab + 16384;

        #pragma unroll
        for (int s = 0; s < 4; s++) {
            uint32_t af[4][4], bf[2][4];
            const int ac = ((2 * s + aHi) ^ i7) << 4;
            #pragma unroll
            for (int mi = 0; mi < 4; mi++)
                ldsm_x4(af[mi], Ab + (aRow + mi * 16) * 128 + ac);
            const int rowB = s * 16 + (g8 & 1) * 8 + i7;
            #pragma unroll
            for (int db = 0; db < 2; db++) {
                const int nc = warpN * 4 + 2 * db + (g8 >> 1);
                uint32_t addr = Bb + rowB * 256 +
                                (((nc & 8) | ((nc ^ rowB) & 7)) << 4);
                ldsm_x4_t(bf[db], addr);
            }
            #pragma unroll
            for (int mi = 0; mi < 4; mi++)
                #pragma unroll
                for (int ni = 0; ni < 4; ni++)
                    mma_f16(c[mi][ni], af[mi],
                            bf[ni >> 1][(ni & 1) * 2], bf[ni >> 1][(ni & 1) * 2 + 1]);
        }
    }
#undef ISSUE_STAGE

    const int gid = lane >> 2, tig = lane & 3;
    #pragma unroll
    for (int mi = 0; mi < 4; mi++) {
        const int r0 = bm * 128 + warpM * 64 + mi * 16 + gid;
        const int r1 = r0 + 8;
        #pragma unroll
        for (int ni = 0; ni < 4; ni++) {
            const int col = bn * 128 + warpN * 32 + ni * 8 + 2 * tig;
            float v0 = c[mi][ni][0], v1 = c[mi][ni][1];
            float v2 = c[mi][ni][2], v3 = c[mi][ni][3];
            if (EPI == 0) {
                float* C = (float*)Cv;
                float2 o0; o0.x = v0; o0.y = v1;
                float2 o1; o1.x = v2; o1.y = v3;
                *(float2*)(C + (size_t)r0 * N + col) = o0;
                *(float2*)(C + (size_t)r1 * N + col) = o1;
            } else if (EPI == 1) {
                float* C = (float*)Cv;
                const float b0 = bias[col], b1 = bias[col + 1];
                const float2 rA = *(const float2*)(res + (size_t)r0 * N + col);
                const float2 rB = *(const float2*)(res + (size_t)r1 * N + col);
                float2 o0; o0.x = v0 + b0 + rA.x; o0.y = v1 + b1 + rA.y;
                float2 o1; o1.x = v2 + b0 + rB.x; o1.y = v3 + b1 + rB.y;
                *(float2*)(C + (size_t)r0 * N + col) = o0;
                *(float2*)(C + (size_t)r1 * N + col) = o1;
            } else if (EPI == 2) {
                __half* C = (__half*)Cv;
                const float b0 = bias[col], b1 = bias[col + 1];
                v0 += b0; v1 += b1; v2 += b0; v3 += b1;
                v0 = v0 / (1.0f + __expf(-v0));
                v1 = v1 / (1.0f + __expf(-v1));
                v2 = v2 / (1.0f + __expf(-v2));
                v3 = v3 / (1.0f + __expf(-v3));
                *(__half2*)(C + (size_t)r0 * N + col) = __floats2half2_rn(v0, v1);
                *(__half2*)(C + (size_t)r1 * N + col) = __floats2half2_rn(v2, v3);
            } else {
                __half* C = (__half*)Cv;
                const float sc = (blockIdx.z == 0) ? 0.125f : 1.0f;
                *(__half2*)(C + (size_t)r0 * N + col) = __floats2half2_rn(v0*sc, v1*sc);
                *(__half2*)(C + (size_t)r1 * N + col) = __floats2half2_rn(v2*sc, v3*sc);
            }
        }
    }
}

// ---------------- fp16 flash attention (R14: balanced, 4 CTA/SM) --------------
#define NQT (TT / 64)     // 32
__global__ __launch_bounds__(128, 4)
void attn_f16(const __half* __restrict__ q, const __half* __restrict__ k,
              const __half* __restrict__ v, __half* __restrict__ o) {
    __shared__ __align__(16) __half sm[24576];
    const uint32_t sb = smem_u32(sm);
    const uint32_t Kb[2] = { sb + 8192,  sb + 16384 };
    const uint32_t Vb[2] = { sb + 24576, sb + 32768 };

    const int tid  = threadIdx.x;
    const int lane = tid & 31;
    const int warp = tid >> 5;
    const int g8   = lane >> 3;
    const int i7   = lane & 7;
    const int gid  = lane >> 2;
    const int tig  = lane & 3;
    const int h = blockIdx.y, b = blockIdx.z;
    const size_t base = ((size_t)b * TT) * DD + (size_t)h * HDIM;

    const __half* kg = k + base;
    const __half* vg = v + base;
    const uint32_t Pw = sb + 40960 + warp * 2048;
    char* Pg = (char*)sm + 40960 + warp * 2048;

    #pragma unroll
    for (int pass = 0; pass < 2; pass++) {
        const int qt = (pass == 0) ? blockIdx.x : (NQT - 1 - blockIdx.x);
        const __half* qg = q + base + (size_t)qt * 64 * DD;

        #pragma unroll
        for (int p = 0; p < 4; p++) {
            int idx = tid + p * 128;
            int row = idx >> 3, ch = idx & 7;
            uint32_t dst = (row * 64 + ((ch ^ (row & 7)) << 3)) * 2;
            cp16(sb + dst,    qg + (size_t)row * DD + ch * 8);
            cp16(Kb[0] + dst, kg + (size_t)row * DD + ch * 8);
            cp16(Vb[0] + dst, vg + (size_t)row * DD + ch * 8);
        }
        asm volatile("cp.async.commit_group;\n");

        uint32_t qf[4][4];
        float oacc[8][4];
        #pragma unroll
        for (int nt = 0; nt < 8; nt++)
            #pragma unroll
            for (int u = 0; u < 4; u++) oacc[nt][u] = 0.f;

        float m0 = -INFINITY, m1 = -INFINITY, l0 = 0.f, l1 = 0.f;
        const int r0 = qt * 64 + warp * 16 + gid;
        const int r1 = r0 + 8;

        for (int kt = 0; kt <= qt; kt++) {
            const int cur = kt & 1;
            if (kt < qt) {
                const int nxt = (kt + 1) & 1;
                #pragma unroll
                for (int p = 0; p < 4; p++) {
                    int idx = tid + p * 128;
                    int row = idx >> 3, ch = idx & 7;
                    uint32_t dst = (row * 64 + ((ch ^ (row & 7)) << 3)) * 2;
                    const size_t gro = (size_t)((kt + 1) * 64 + row) * DD + ch * 8;
                    cp16(Kb[nxt] + dst, kg + gro);
                    cp16(Vb[nxt] + dst, vg + gro);
                }
                asm volatile("cp.async.commit_group;\n");
                asm volatile("cp.async.wait_group 1;\n");
            } else {
                asm volatile("cp.async.wait_group 0;\n");
            }
            __syncthreads();

            if (kt == 0) {
                const int rowQ = warp * 16 + (g8 & 1) * 8 + i7;
                #pragma unroll
                for (int s4 = 0; s4 < 4; s4++) {
                    uint32_t addr = sb +
                        (rowQ * 64 + (((2 * s4 + (g8 >> 1)) ^ (rowQ & 7)) << 3)) * 2;
                    ldsm_x4(qf[s4], addr);
                }
            }

            float s[8][4];
            #pragma unroll
            for (int nt = 0; nt < 8; nt++)
                s[nt][0] = s[nt][1] = s[nt][2] = s[nt][3] = 0.f;
            #pragma unroll
            for (int s4 = 0; s4 < 4; s4++) {
                #pragma unroll
                for (int ntb = 0; ntb < 4; ntb++) {
                    const int rowK = ntb * 16 + (g8 >> 1) * 8 + i7;
                    uint32_t addr = Kb[cur] + (rowK * 64 +
                                    (((2 * s4 + (g8 & 1)) ^ (rowK & 7)) << 3)) * 2;
                    uint32_t bf[4];
                    ldsm_x4(bf, addr);
                    mma_f16(s[2 * ntb],     qf[s4], bf[0], bf[1]);
                    mma_f16(s[2 * ntb + 1], qf[s4], bf[2], bf[3]);
                }
            }

            if (kt == qt) {
                #pragma unroll
                for (int nt = 0; nt < 8; nt++) {
                    int cc = kt * 64 + nt * 8 + 2 * tig;
                    if (cc     > r0) s[nt][0] = -INFINITY;
                    if (cc + 1 > r0) s[nt][1] = -INFINITY;
                    if (cc     > r1) s[nt][2] = -INFINITY;
                    if (cc + 1 > r1) s[nt][3] = -INFINITY;
                }
            }

            float mt0 = -INFINITY, mt1 = -INFINITY;
            #pragma unroll
            for (int nt = 0; nt < 8; nt++) {
                mt0 = fmaxf(mt0, fmaxf(s[nt][0], s[nt][1]));
                mt1 = fmaxf(mt1, fmaxf(s[nt][2], s[nt][3]));
            }
            mt0 = fmaxf(mt0, __shfl_xor_sync(0xFFFFFFFFu, mt0, 1));
            mt0 = fmaxf(mt0, __shfl_xor_sync(0xFFFFFFFFu, mt0, 2));
            mt1 = fmaxf(mt1, __shfl_xor_sync(0xFFFFFFFFu, mt1, 1));
            mt1 = fmaxf(mt1, __shfl_xor_sync(0xFFFFFFFFu, mt1, 2));
            const float mn0 = fmaxf(m0, mt0), mn1 = fmaxf(m1, mt1);
            const float a0 = __expf(m0 - mn0), a1 = __expf(m1 - mn1);

            float ls0 = 0.f, ls1 = 0.f;
            #pragma unroll
            for (int nt = 0; nt < 8; nt++) {
                float p0 = __expf(s[nt][0] - mn0);
                float p1 = __expf(s[nt][1] - mn0);
                float p2 = __expf(s[nt][2] - mn1);
                float p3 = __expf(s[nt][3] - mn1);
                ls0 += p0 + p1; ls1 += p2 + p3;
                const int rA = gid, rB = gid + 8;
                *(__half2*)(Pg + (rA * 64 + ((nt ^ (rA & 7)) << 3) + 2 * tig) * 2) =
                    __floats2half2_rn(p0, p1);
                *(__half2*)(Pg + (rB * 64 + ((nt ^ (rB & 7)) << 3) + 2 * tig) * 2) =
                    __floats2half2_rn(p2, p3);
            }
            ls0 += __shfl_xor_sync(0xFFFFFFFFu, ls0, 1);
            ls0 += __shfl_xor_sync(0xFFFFFFFFu, ls0, 2);
            ls1 += __shfl_xor_sync(0xFFFFFFFFu, ls1, 1);
            ls1 += __shfl_xor_sync(0xFFFFFFFFu, ls1, 2);
            l0 = l0 * a0 + ls0;
            l1 = l1 * a1 + ls1;
            m0 = mn0; m1 = mn1;

            #pragma unroll
            for (int nt = 0; nt < 8; nt++) {
                oacc[nt][0] *= a0; oacc[nt][1] *= a0;
                oacc[nt][2] *= a1; oacc[nt][3] *= a1;
            }
            __syncwarp();

            #pragma unroll
            for (int s4 = 0; s4 < 4; s4++) {
                uint32_t pf[4];
                const int rowP = (g8 & 1) * 8 + i7;
                ldsm_x4(pf, Pw + (rowP * 64 +
                        (((2 * s4 + (g8 >> 1)) ^ (rowP & 7)) << 3)) * 2);
                const int rowV = s4 * 16 + (g8 & 1) * 8 + i7;
                #pragma unroll
                for (int db = 0; db < 4; db++) {
                    uint32_t bf[4];
                    uint32_t addr = Vb[cur] + (rowV * 64 +
                                    (((2 * db + (g8 >> 1)) ^ (rowV & 7)) << 3)) * 2;
                    ldsm_x4_t(bf, addr);
                    mma_f16(oacc[2 * db],     pf, bf[0], bf[1]);
                    mma_f16(oacc[2 * db + 1], pf, bf[2], bf[3]);
                }
            }
            __syncthreads();
        }

        const float li0 = 1.0f / l0, li1 = 1.0f / l1;
        __half* og = o + base;
        #pragma unroll
        for (int nt = 0; nt < 8; nt++) {
            const int col = nt * 8 + 2 * tig;
            *(__half2*)(og + (size_t)r0 * DD + col) =
                __floats2half2_rn(oacc[nt][0] * li0, oacc[nt][1] * li0);
            *(__half2*)(og + (size_t)r1 * DD + col) =
                __floats2half2_rn(oacc[nt][2] * li1, oacc[nt][3] * li1);
        }
    }
}

// ---------------- launch ----------------
extern "C" void kernel_launch(void* const* d_in, const int* in_sizes, int n_in,
                              void* d_out, int out_size) {
    const float* x     = (const float*)d_in[0];
    const float* Wq    = (const float*)d_in[2];
    const float* Wk    = (const float*)d_in[3];
    const float* Wv    = (const float*)d_in[4];
    const float* Wo    = (const float*)d_in[5];
    const float* bo    = (const float*)d_in[6];
    const float* W1    = (const float*)d_in[7];
    const float* b1    = (const float*)d_in[8];
    const float* W2    = (const float*)d_in[9];
    const float* b2    = (const float*)d_in[10];
    const float* gattn = (const float*)d_in[11];
    const float* gff   = (const float*)d_in[12];
    float* out = (float*)d_out;

    __half *xa, *q, *k, *v, *at, *hb, *wh;
    float *x1;
    cudaGetSymbolAddress((void**)&xa, g_xa);
    cudaGetSymbolAddress((void**)&q,  g_q);
    cudaGetSymbolAddress((void**)&k,  g_k);
    cudaGetSymbolAddress((void**)&v,  g_v);
    cudaGetSymbolAddress((void**)&at, g_at);
    cudaGetSymbolAddress((void**)&x1, g_x1);
    cudaGetSymbolAddress((void**)&hb, g_h);
    cudaGetSymbolAddress((void**)&wh, g_wh);

    __half* Wq_h = wh;
    __half* Wk_h = wh + (size_t)1*1024*1024;
    __half* Wv_h = wh + (size_t)2*1024*1024;
    __half* Wo_h = wh + (size_t)3*1024*1024;
    __half* W1_h = wh + (size_t)4*1024*1024;
    __half* W2_h = wh + (size_t)8*1024*1024;

    cudaFuncSetAttribute(gemm_f16<1>, cudaFuncAttributeMaxDynamicSharedMemorySize, GEMM_SMEM);
    cudaFuncSetAttribute(gemm_f16<2>, cudaFuncAttributeMaxDynamicSharedMemorySize, GEMM_SMEM);
    cudaFuncSetAttribute(gemm_f16<3>, cudaFuncAttributeMaxDynamicSharedMemorySize, GEMM_SMEM);

    // 0. fused fp32 -> fp16 weight convert (one launch)
    convert_all<<<2048, 256>>>((const float4*)Wq, (const float4*)Wk,
                               (const float4*)Wv, (const float4*)Wo,
                               (const float4*)W1, (const float4*)W2,
                               (uint4*)wh);

    // 1. rmsnorm(x, g_attn) -> xa (fp16)
    rmsnorm_kernel<<<ROWS, 256>>>(x, gattn, xa);

    // 2. QKV projections (fp16 out; Q pre-scaled by 0.125)
    {
        dim3 grid(DD / 128, ROWS / 128, 3);
        gemm_f16<3><<<grid, 256, GEMM_SMEM>>>(xa, Wq_h, Wk_h, Wv_h,
                                              q, k, v, nullptr, nullptr, DD, DD);
    }

    // 3. causal attention (balanced 2 q-tiles per CTA) -> at (fp16)
    {
        dim3 grid(TT / 128, HH, BB);
        attn_f16<<<grid, 128>>>(q, k, v, at);
    }

    // 4. x1 = x + at @ Wo + bo
    {
        dim3 grid(DD / 128, ROWS / 128, 1);
        gemm_f16<1><<<grid, 256, GEMM_SMEM>>>(at, Wo_h, Wo_h, Wo_h,
                                              x1, x1, x1, bo, x, DD, DD);
    }

    // 5. rmsnorm(x1, g_ff) -> xa (fp16)
    rmsnorm_kernel<<<ROWS, 256>>>(x1, gff, xa);

    // 6. h = silu(xa @ W1 + b1) -> hb (fp16)
    {
        dim3 grid(FF / 128, ROWS / 128, 1);
        gemm_f16<2><<<grid, 256, GEMM_SMEM>>>(xa, W1_h, W1_h, W1_h,
                                              hb, hb, hb, b1, nullptr, FF, DD);
    }

    // 7. out = x1 + hb @ W2 + b2
    {
        dim3 grid(DD / 128, ROWS / 128, 1);
        gemm_f16<1><<<grid, 256, GEMM_SMEM>>>(hb, W2_h, W2_h, W2_h,
                                              out, out, out, b2, x1, DD, FF);
    }
}

// round 16
// speedup vs baseline: 1.0201x; 1.0201x over previous
#include <cuda_runtime.h>
#include <cuda_fp16.h>
#include <cstdint>

// ---------------- problem constants ----------------
#define BB   2
#define TT   2048
#define DD   1024
#define HH   16
#define HDIM 64
#define FF   4096
#define ROWS (BB*TT)          // 4096

// ---------------- scratch (device globals) ----------------
__device__ __half g_xa [ROWS*DD];
__device__ __half g_q  [ROWS*DD];
__device__ __half g_k  [ROWS*DD];
__device__ __half g_v  [ROWS*DD];
__device__ __half g_at [ROWS*DD];
__device__ float  g_x1 [ROWS*DD];
__device__ __half g_h  [(size_t)ROWS*FF];
__device__ __half g_wh [(size_t)12*1024*1024];

// ---------------- helpers ----------------
__device__ __forceinline__ uint32_t smem_u32(const void* p) {
    return (uint32_t)__cvta_generic_to_shared(p);
}
__device__ __forceinline__ void mma_f16(float* c, const uint32_t* a,
                                        uint32_t b0, uint32_t b1) {
    asm volatile(
        "mma.sync.aligned.m16n8k16.row.col.f32.f16.f16.f32 "
        "{%0,%1,%2,%3},{%4,%5,%6,%7},{%8,%9},{%0,%1,%2,%3};\n"
        : "+f"(c[0]), "+f"(c[1]), "+f"(c[2]), "+f"(c[3])
        : "r"(a[0]), "r"(a[1]), "r"(a[2]), "r"(a[3]), "r"(b0), "r"(b1));
}
__device__ __forceinline__ void ldsm_x4(uint32_t* r, uint32_t saddr) {
    asm volatile("ldmatrix.sync.aligned.m8n8.x4.shared.b16 {%0,%1,%2,%3}, [%4];"
                 : "=r"(r[0]), "=r"(r[1]), "=r"(r[2]), "=r"(r[3]) : "r"(saddr));
}
__device__ __forceinline__ void ldsm_x4_t(uint32_t* r, uint32_t saddr) {
    asm volatile("ldmatrix.sync.aligned.m8n8.x4.trans.shared.b16 {%0,%1,%2,%3}, [%4];"
                 : "=r"(r[0]), "=r"(r[1]), "=r"(r[2]), "=r"(r[3]) : "r"(saddr));
}
__device__ __forceinline__ void cp16(uint32_t saddr, const void* g) {
    asm volatile("cp.async.cg.shared.global [%0], [%1], 16;\n" :: "r"(saddr), "l"(g));
}

// ---------------- fused weight convert fp32 -> fp16 ----------------
#define CVT_TOTAL 1572864
__global__ __launch_bounds__(256)
void convert_all(const float4* __restrict__ wq, const float4* __restrict__ wk,
                 const float4* __restrict__ wv, const float4* __restrict__ wo,
                 const float4* __restrict__ w1, const float4* __restrict__ w2,
                 uint4* __restrict__ dst) {
    const int nth = gridDim.x * 256;
    for (int i = blockIdx.x * 256 + threadIdx.x; i < CVT_TOTAL; i += nth) {
        const float4* src;
        int off;
        if (i < 524288) {
            int r = i >> 17;
            src = (r == 0) ? wq : (r == 1) ? wk : (r == 2) ? wv : wo;
            off = i & 131071;
        } else if (i < 1048576) {
            src = w1; off = i - 524288;
        } else {
            src = w2; off = i - 1048576;
        }
        float4 a = src[2 * off], b = src[2 * off + 1];
        __half2 h0 = __floats2half2_rn(a.x, a.y);
        __half2 h1 = __floats2half2_rn(a.z, a.w);
        __half2 h2 = __floats2half2_rn(b.x, b.y);
        __half2 h3 = __floats2half2_rn(b.z, b.w);
        uint4 o;
        o.x = *(uint32_t*)&h0; o.y = *(uint32_t*)&h1;
        o.z = *(uint32_t*)&h2; o.w = *(uint32_t*)&h3;
        dst[i] = o;
    }
}

// ---------------- rmsnorm (fp16 output) ----------------
__global__ __launch_bounds__(256)
void rmsnorm_kernel(const float* __restrict__ x, const float* __restrict__ g,
                    __half* __restrict__ out) {
    __shared__ float red[256];
    const int row = blockIdx.x;
    const int tid = threadIdx.x;
    const float4 v = ((const float4*)(x + (size_t)row * DD))[tid];
    float ss = v.x*v.x + v.y*v.y + v.z*v.z + v.w*v.w;
    red[tid] = ss;
    __syncthreads();
    #pragma unroll
    for (int s = 128; s > 0; s >>= 1) {
        if (tid < s) red[tid] += red[tid + s];
        __syncthreads();
    }
    const float norm = rsqrtf(red[0] * (1.0f / DD) + 1e-5f);
    const float4 gv = ((const float4*)g)[tid];
    __half2 h01 = __floats2half2_rn(v.x * norm * gv.x, v.y * norm * gv.y);
    __half2 h23 = __floats2half2_rn(v.z * norm * gv.z, v.w * norm * gv.w);
    uint2 pk; pk.x = *(uint32_t*)&h01; pk.y = *(uint32_t*)&h23;
    ((uint2*)(out + (size_t)row * DD))[tid] = pk;
}

// ---------------- fp16 tensor-core GEMM (256 thr, 16 warps/SM) ----------------
#define SGS3 3
#define STG_BYTES 32768
#define GEMM_SMEM (SGS3 * STG_BYTES)

template <int EPI>
__global__ __launch_bounds__(256, 2)
void gemm_f16(const __half* __restrict__ A,
              const __half* __restrict__ B0, const __half* __restrict__ B1,
              const __half* __restrict__ B2,
              void* C0v, void* C1v, void* C2v,
              const float* __restrict__ bias, const float* __restrict__ res,
              int N, int K) {
    extern __shared__ __align__(16) char dynsm[];
    const uint32_t sb = smem_u32(dynsm);

    const __half* Bw = (blockIdx.z == 0) ? B0 : (blockIdx.z == 1 ? B1 : B2);
    void* Cv = (blockIdx.z == 0) ? C0v : (blockIdx.z == 1 ? C1v : C2v);

    const int tid   = threadIdx.x;
    const int lane  = tid & 31;
    const int warp  = tid >> 5;
    const int warpM = warp & 1;
    const int warpN = warp >> 1;
    const int g8    = lane >> 3;
    const int i7    = lane & 7;

    const int bm = blockIdx.y, bn = blockIdx.x;
    const __half* Aq = A  + (size_t)bm * 128 * K;
    const __half* Bq = Bw + bn * 128;

    const int aRow = warpM * 64 + (g8 & 1) * 8 + i7;
    const int aHi  = g8 >> 1;

    int arow[4], ach[4], asw[4], brow[4], bch[4], bsw[4];
    #pragma unroll
    for (int p = 0; p < 4; p++) {
        int idx = tid + p * 256;
        arow[p] = idx >> 3;  ach[p] = idx & 7;
        asw[p]  = ach[p] ^ (arow[p] & 7);
        brow[p] = idx >> 4;  bch[p] = idx & 15;
        bsw[p]  = (bch[p] & 8) | ((bch[p] ^ brow[p]) & 7);
    }

#define ISSUE_STAGE(st, kb)                                                    \
    {                                                                          \
        uint32_t Ab = sb + (st) * STG_BYTES;                                   \
        uint32_t Bb = Ab + 16384;                                              \
        _Pragma("unroll")                                                      \
        for (int p = 0; p < 4; p++) {                                          \
            cp16(Ab + arow[p] * 128 + asw[p] * 16,                             \
                 Aq + (size_t)arow[p] * K + (kb) + ach[p] * 8);                \
            cp16(Bb + brow[p] * 256 + bsw[p] * 16,                             \
                 Bq + (size_t)((kb) + brow[p]) * N + bch[p] * 8);              \
        }                                                                      \
        asm volatile("cp.async.commit_group;\n");                              \
    }

    float c[4][4][4];
    #pragma unroll
    for (int mi = 0; mi < 4; mi++)
        #pragma unroll
        for (int ni = 0; ni < 4; ni++)
            #pragma unroll
            for (int u = 0; u < 4; u++) c[mi][ni][u] = 0.f;

    const int ktiles = K >> 6;

    ISSUE_STAGE(0, 0);
    ISSUE_STAGE(1, 64);

    for (int u = 0; u < ktiles; u++) {
        asm volatile("cp.async.wait_group 1;\n");
        __syncthreads();

        if (u + 2 < ktiles) {
            const int stn = (u + 2) % SGS3;
            ISSUE_STAGE(stn, (u + 2) * 64);
        } else {
            asm volatile("cp.async.commit_group;\n");
        }

        const int st = u % SGS3;
        const uint32_t Ab = sb + st * STG_BYTES;
        const uint32_t Bb = Ab + 16384;

        #pragma unroll
        for (int s = 0; s < 4; s++) {
            uint32_t af[4][4], bf[2][4];
            const int ac = ((2 * s + aHi) ^ i7) << 4;
            #pragma unroll
            for (int mi = 0; mi < 4; mi++)
                ldsm_x4(af[mi], Ab + (aRow + mi * 16) * 128 + ac);
            const int rowB = s * 16 + (g8 & 1) * 8 + i7;
            #pragma unroll
            for (int db = 0; db < 2; db++) {
                const int nc = warpN * 4 + 2 * db + (g8 >> 1);
                uint32_t addr = Bb + rowB * 256 +
                                (((nc & 8) | ((nc ^ rowB) & 7)) << 4);
                ldsm_x4_t(bf[db], addr);
            }
            #pragma unroll
            for (int mi = 0; mi < 4; mi++)
                #pragma unroll
                for (int ni = 0; ni < 4; ni++)
                    mma_f16(c[mi][ni], af[mi],
                            bf[ni >> 1][(ni & 1) * 2], bf[ni >> 1][(ni & 1) * 2 + 1]);
        }
    }
#undef ISSUE_STAGE

    const int gid = lane >> 2, tig = lane & 3;
    #pragma unroll
    for (int mi = 0; mi < 4; mi++) {
        const int r0 = bm * 128 + warpM * 64 + mi * 16 + gid;
        const int r1 = r0 + 8;
        #pragma unroll
        for (int ni = 0; ni < 4; ni++) {
            const int col = bn * 128 + warpN * 32 + ni * 8 + 2 * tig;
            float v0 = c[mi][ni][0], v1 = c[mi][ni][1];
            float v2 = c[mi][ni][2], v3 = c[mi][ni][3];
            if (EPI == 0) {
                float* C = (float*)Cv;
                float2 o0; o0.x = v0; o0.y = v1;
                float2 o1; o1.x = v2; o1.y = v3;
                *(float2*)(C + (size_t)r0 * N + col) = o0;
                *(float2*)(C + (size_t)r1 * N + col) = o1;
            } else if (EPI == 1) {
                float* C = (float*)Cv;
                const float b0 = bias[col], b1 = bias[col + 1];
                const float2 rA = *(const float2*)(res + (size_t)r0 * N + col);
                const float2 rB = *(const float2*)(res + (size_t)r1 * N + col);
                float2 o0; o0.x = v0 + b0 + rA.x; o0.y = v1 + b1 + rA.y;
                float2 o1; o1.x = v2 + b0 + rB.x; o1.y = v3 + b1 + rB.y;
                *(float2*)(C + (size_t)r0 * N + col) = o0;
                *(float2*)(C + (size_t)r1 * N + col) = o1;
            } else if (EPI == 2) {
                __half* C = (__half*)Cv;
                const float b0 = bias[col], b1 = bias[col + 1];
                v0 += b0; v1 += b1; v2 += b0; v3 += b1;
                v0 = v0 / (1.0f + __expf(-v0));
                v1 = v1 / (1.0f + __expf(-v1));
                v2 = v2 / (1.0f + __expf(-v2));
                v3 = v3 / (1.0f + __expf(-v3));
                *(__half2*)(C + (size_t)r0 * N + col) = __floats2half2_rn(v0, v1);
                *(__half2*)(C + (size_t)r1 * N + col) = __floats2half2_rn(v2, v3);
            } else {
                __half* C = (__half*)Cv;
                const float sc = (blockIdx.z == 0) ? 0.125f : 1.0f;
                *(__half2*)(C + (size_t)r0 * N + col) = __floats2half2_rn(v0*sc, v1*sc);
                *(__half2*)(C + (size_t)r1 * N + col) = __floats2half2_rn(v2*sc, v3*sc);
            }
        }
    }
}

// ---------------- fp16 flash attention: P kept in registers -------------------
// S C-fragment == P@V A-fragment layout; no P smem round-trip.
// BYTE layout: Q [0,8K), K0 [8K,16K), K1 [16K,24K), V0 [24K,32K), V1 [32K,40K)
#define NQT (TT / 64)     // 32
__global__ __launch_bounds__(128, 4)
void attn_f16(const __half* __restrict__ q, const __half* __restrict__ k,
              const __half* __restrict__ v, __half* __restrict__ o) {
    __shared__ __align__(16) __half sm[20480];
    const uint32_t sb = smem_u32(sm);
    const uint32_t Kb[2] = { sb + 8192,  sb + 16384 };
    const uint32_t Vb[2] = { sb + 24576, sb + 32768 };

    const int tid  = threadIdx.x;
    const int lane = tid & 31;
    const int warp = tid >> 5;
    const int g8   = lane >> 3;
    const int i7   = lane & 7;
    const int gid  = lane >> 2;
    const int tig  = lane & 3;
    const int h = blockIdx.y, b = blockIdx.z;
    const size_t base = ((size_t)b * TT) * DD + (size_t)h * HDIM;

    const __half* kg = k + base;
    const __half* vg = v + base;

    #pragma unroll
    for (int pass = 0; pass < 2; pass++) {
        const int qt = (pass == 0) ? blockIdx.x : (NQT - 1 - blockIdx.x);
        const __half* qg = q + base + (size_t)qt * 64 * DD;

        #pragma unroll
        for (int p = 0; p < 4; p++) {
            int idx = tid + p * 128;
            int row = idx >> 3, ch = idx & 7;
            uint32_t dst = (row * 64 + ((ch ^ (row & 7)) << 3)) * 2;
            cp16(sb + dst,    qg + (size_t)row * DD + ch * 8);
            cp16(Kb[0] + dst, kg + (size_t)row * DD + ch * 8);
            cp16(Vb[0] + dst, vg + (size_t)row * DD + ch * 8);
        }
        asm volatile("cp.async.commit_group;\n");

        uint32_t qf[4][4];
        float oacc[8][4];
        #pragma unroll
        for (int nt = 0; nt < 8; nt++)
            #pragma unroll
            for (int u = 0; u < 4; u++) oacc[nt][u] = 0.f;

        float m0 = -INFINITY, m1 = -INFINITY, l0 = 0.f, l1 = 0.f;
        const int r0 = qt * 64 + warp * 16 + gid;
        const int r1 = r0 + 8;

        for (int kt = 0; kt <= qt; kt++) {
            const int cur = kt & 1;
            if (kt < qt) {
                const int nxt = (kt + 1) & 1;
                #pragma unroll
                for (int p = 0; p < 4; p++) {
                    int idx = tid + p * 128;
                    int row = idx >> 3, ch = idx & 7;
                    uint32_t dst = (row * 64 + ((ch ^ (row & 7)) << 3)) * 2;
                    const size_t gro = (size_t)((kt + 1) * 64 + row) * DD + ch * 8;
                    cp16(Kb[nxt] + dst, kg + gro);
                    cp16(Vb[nxt] + dst, vg + gro);
                }
                asm volatile("cp.async.commit_group;\n");
                asm volatile("cp.async.wait_group 1;\n");
            } else {
                asm volatile("cp.async.wait_group 0;\n");
            }
            __syncthreads();

            if (kt == 0) {
                const int rowQ = warp * 16 + (g8 & 1) * 8 + i7;
                #pragma unroll
                for (int s4 = 0; s4 < 4; s4++) {
                    uint32_t addr = sb +
                        (rowQ * 64 + (((2 * s4 + (g8 >> 1)) ^ (rowQ & 7)) << 3)) * 2;
                    ldsm_x4(qf[s4], addr);
                }
            }

            // ---- S = Q @ K^T ----
            float s[8][4];
            #pragma unroll
            for (int nt = 0; nt < 8; nt++)
                s[nt][0] = s[nt][1] = s[nt][2] = s[nt][3] = 0.f;
            #pragma unroll
            for (int s4 = 0; s4 < 4; s4++) {
                #pragma unroll
                for (int ntb = 0; ntb < 4; ntb++) {
                    const int rowK = ntb * 16 + (g8 >> 1) * 8 + i7;
                    uint32_t addr = Kb[cur] + (rowK * 64 +
                                    (((2 * s4 + (g8 & 1)) ^ (rowK & 7)) << 3)) * 2;
                    uint32_t bf[4];
                    ldsm_x4(bf, addr);
                    mma_f16(s[2 * ntb],     qf[s4], bf[0], bf[1]);
                    mma_f16(s[2 * ntb + 1], qf[s4], bf[2], bf[3]);
                }
            }

            if (kt == qt) {
                #pragma unroll
                for (int nt = 0; nt < 8; nt++) {
                    int cc = kt * 64 + nt * 8 + 2 * tig;
                    if (cc     > r0) s[nt][0] = -INFINITY;
                    if (cc + 1 > r0) s[nt][1] = -INFINITY;
                    if (cc     > r1) s[nt][2] = -INFINITY;
                    if (cc + 1 > r1) s[nt][3] = -INFINITY;
                }
            }

            // ---- online softmax; pack P into A-fragment registers ----
            float mt0 = -INFINITY, mt1 = -INFINITY;
            #pragma unroll
            for (int nt = 0; nt < 8; nt++) {
                mt0 = fmaxf(mt0, fmaxf(s[nt][0], s[nt][1]));
                mt1 = fmaxf(mt1, fmaxf(s[nt][2], s[nt][3]));
            }
            mt0 = fmaxf(mt0, __shfl_xor_sync(0xFFFFFFFFu, mt0, 1));
            mt0 = fmaxf(mt0, __shfl_xor_sync(0xFFFFFFFFu, mt0, 2));
            mt1 = fmaxf(mt1, __shfl_xor_sync(0xFFFFFFFFu, mt1, 1));
            mt1 = fmaxf(mt1, __shfl_xor_sync(0xFFFFFFFFu, mt1, 2));
            const float mn0 = fmaxf(m0, mt0), mn1 = fmaxf(m1, mt1);
            const float a0 = __expf(m0 - mn0), a1 = __expf(m1 - mn1);

            uint32_t ph[8][2];
            float ls0 = 0.f, ls1 = 0.f;
            #pragma unroll
            for (int nt = 0; nt < 8; nt++) {
                float p0 = __expf(s[nt][0] - mn0);
                float p1 = __expf(s[nt][1] - mn0);
                float p2 = __expf(s[nt][2] - mn1);
                float p3 = __expf(s[nt][3] - mn1);
                ls0 += p0 + p1; ls1 += p2 + p3;
                __half2 h01 = __floats2half2_rn(p0, p1);
                __half2 h23 = __floats2half2_rn(p2, p3);
                ph[nt][0] = *(uint32_t*)&h01;   // (row gid,   k 2tig,2tig+1)
                ph[nt][1] = *(uint32_t*)&h23;   // (row gid+8, k 2tig,2tig+1)
            }
            ls0 += __shfl_xor_sync(0xFFFFFFFFu, ls0, 1);
            ls0 += __shfl_xor_sync(0xFFFFFFFFu, ls0, 2);
            ls1 += __shfl_xor_sync(0xFFFFFFFFu, ls1, 1);
            ls1 += __shfl_xor_sync(0xFFFFFFFFu, ls1, 2);
            l0 = l0 * a0 + ls0;
            l1 = l1 * a1 + ls1;
            m0 = mn0; m1 = mn1;

            #pragma unroll
            for (int nt = 0; nt < 8; nt++) {
                oacc[nt][0] *= a0; oacc[nt][1] *= a0;
                oacc[nt][2] *= a1; oacc[nt][3] *= a1;
            }

            // ---- O += P @ V (P fragments straight from registers) ----
            #pragma unroll
            for (int s4 = 0; s4 < 4; s4++) {
                uint32_t pf[4];
                pf[0] = ph[2 * s4][0];
                pf[1] = ph[2 * s4][1];
                pf[2] = ph[2 * s4 + 1][0];
                pf[3] = ph[2 * s4 + 1][1];
                const int rowV = s4 * 16 + (g8 & 1) * 8 + i7;
                #pragma unroll
                for (int db = 0; db < 4; db++) {
                    uint32_t bf[4];
                    uint32_t addr = Vb[cur] + (rowV * 64 +
                                    (((2 * db + (g8 >> 1)) ^ (rowV & 7)) << 3)) * 2;
                    ldsm_x4_t(bf, addr);
                    mma_f16(oacc[2 * db],     pf, bf[0], bf[1]);
                    mma_f16(oacc[2 * db + 1], pf, bf[2], bf[3]);
                }
            }
            __syncthreads();   // protect K/V buffer reuse by next prefetch
        }

        const float li0 = 1.0f / l0, li1 = 1.0f / l1;
        __half* og = o + base;
        #pragma unroll
        for (int nt = 0; nt < 8; nt++) {
            const int col = nt * 8 + 2 * tig;
            *(__half2*)(og + (size_t)r0 * DD + col) =
                __floats2half2_rn(oacc[nt][0] * li0, oacc[nt][1] * li0);
            *(__half2*)(og + (size_t)r1 * DD + col) =
                __floats2half2_rn(oacc[nt][2] * li1, oacc[nt][3] * li1);
        }
    }
}

// ---------------- launch ----------------
extern "C" void kernel_launch(void* const* d_in, const int* in_sizes, int n_in,
                              void* d_out, int out_size) {
    const float* x     = (const float*)d_in[0];
    const float* Wq    = (const float*)d_in[2];
    const float* Wk    = (const float*)d_in[3];
    const float* Wv    = (const float*)d_in[4];
    const float* Wo    = (const float*)d_in[5];
    const float* bo    = (const float*)d_in[6];
    const float* W1    = (const float*)d_in[7];
    const float* b1    = (const float*)d_in[8];
    const float* W2    = (const float*)d_in[9];
    const float* b2    = (const float*)d_in[10];
    const float* gattn = (const float*)d_in[11];
    const float* gff   = (const float*)d_in[12];
    float* out = (float*)d_out;

    __half *xa, *q, *k, *v, *at, *hb, *wh;
    float *x1;
    cudaGetSymbolAddress((void**)&xa, g_xa);
    cudaGetSymbolAddress((void**)&q,  g_q);
    cudaGetSymbolAddress((void**)&k,  g_k);
    cudaGetSymbolAddress((void**)&v,  g_v);
    cudaGetSymbolAddress((void**)&at, g_at);
    cudaGetSymbolAddress((void**)&x1, g_x1);
    cudaGetSymbolAddress((void**)&hb, g_h);
    cudaGetSymbolAddress((void**)&wh, g_wh);

    __half* Wq_h = wh;
    __half* Wk_h = wh + (size_t)1*1024*1024;
    __half* Wv_h = wh + (size_t)2*1024*1024;
    __half* Wo_h = wh + (size_t)3*1024*1024;
    __half* W1_h = wh + (size_t)4*1024*1024;
    __half* W2_h = wh + (size_t)8*1024*1024;

    cudaFuncSetAttribute(gemm_f16<1>, cudaFuncAttributeMaxDynamicSharedMemorySize, GEMM_SMEM);
    cudaFuncSetAttribute(gemm_f16<2>, cudaFuncAttributeMaxDynamicSharedMemorySize, GEMM_SMEM);
    cudaFuncSetAttribute(gemm_f16<3>, cudaFuncAttributeMaxDynamicSharedMemorySize, GEMM_SMEM);

    // 0. fused fp32 -> fp16 weight convert (one launch)
    convert_all<<<2048, 256>>>((const float4*)Wq, (const float4*)Wk,
                               (const float4*)Wv, (const float4*)Wo,
                               (const float4*)W1, (const float4*)W2,
                               (uint4*)wh);

    // 1. rmsnorm(x, g_attn) -> xa (fp16)
    rmsnorm_kernel<<<ROWS, 256>>>(x, gattn, xa);

    // 2. QKV projections (fp16 out; Q pre-scaled by 0.125)
    {
        dim3 grid(DD / 128, ROWS / 128, 3);
        gemm_f16<3><<<grid, 256, GEMM_SMEM>>>(xa, Wq_h, Wk_h, Wv_h,
                                              q, k, v, nullptr, nullptr, DD, DD);
    }

    // 3. causal attention (register-P, balanced) -> at (fp16)
    {
        dim3 grid(TT / 128, HH, BB);
        attn_f16<<<grid, 128>>>(q, k, v, at);
    }

    // 4. x1 = x + at @ Wo + bo
    {
        dim3 grid(DD / 128, ROWS / 128, 1);
        gemm_f16<1><<<grid, 256, GEMM_SMEM>>>(at, Wo_h, Wo_h, Wo_h,
                                              x1, x1, x1, bo, x, DD, DD);
    }

    // 5. rmsnorm(x1, g_ff) -> xa (fp16)
    rmsnorm_kernel<<<ROWS, 256>>>(x1, gff, xa);

    // 6. h = silu(xa @ W1 + b1) -> hb (fp16)
    {
        dim3 grid(FF / 128, ROWS / 128, 1);
        gemm_f16<2><<<grid, 256, GEMM_SMEM>>>(xa, W1_h, W1_h, W1_h,
                                              hb, hb, hb, b1, nullptr, FF, DD);
    }

    // 7. out = x1 + hb @ W2 + b2
    {
        dim3 grid(DD / 128, ROWS / 128, 1);
        gemm_f16<1><<<grid, 256, GEMM_SMEM>>>(hb, W2_h, W2_h, W2_h,
                                              out, out, out, b2, x1, DD, FF);
    }
}